// round 14
// baseline (speedup 1.0000x reference)
#include <cuda_runtime.h>
#include <cuda_fp16.h>
#include <math.h>
#include <stdint.h>

#define T_TOK 2048
#define D_DIM 768
#define E_EXP 8
#define K_TOP 2
#define H_DIM 3072
#define NPAD  5120

#define OUT_IDS  (T_TOK * D_DIM)
#define OUT_LOSS (T_TOK * D_DIM + T_TOK * K_TOP)

// ---------------- device scratch ----------------
__device__ int   g_e[T_TOK][K_TOP];
__device__ float g_g[T_TOK][K_TOP];
__device__ int   g_count[E_EXP];
__device__ int   g_offset[E_EXP + 1];
__device__ int   g_cursor[E_EXP];
__device__ float g_smsum[E_EXP];
__device__ int   g_ltok[NPAD];
__device__ float g_slotgate[NPAD];

__device__ __half g_xgh[(size_t)NPAD * D_DIM];
__device__ __half g_w1h[(size_t)E_EXP * D_DIM * H_DIM];
__device__ __half g_w2h[(size_t)E_EXP * D_DIM * H_DIM];
__device__ __half g_wph[(size_t)E_EXP * H_DIM * D_DIM];
__device__ __half g_acth[(size_t)NPAD * H_DIM];

// ---------------- helpers ----------------
__device__ __forceinline__ uint32_t s2u(const void* p) {
    return (uint32_t)__cvta_generic_to_shared(p);
}
__device__ __forceinline__ void cp16(uint32_t dst, const void* src) {
    asm volatile("cp.async.ca.shared.global [%0], [%1], 16;" :: "r"(dst), "l"(src));
}
#define CP_COMMIT() asm volatile("cp.async.commit_group;")
#define CP_WAIT1()  asm volatile("cp.async.wait_group 1;")
#define CP_WAIT0()  asm volatile("cp.async.wait_group 0;")

__device__ __forceinline__ void ldsm4(uint32_t* r, uint32_t addr) {
    asm volatile("ldmatrix.sync.aligned.m8n8.x4.shared.b16 {%0,%1,%2,%3}, [%4];"
        : "=r"(r[0]), "=r"(r[1]), "=r"(r[2]), "=r"(r[3]) : "r"(addr));
}
__device__ __forceinline__ void ldsm4t(uint32_t* r, uint32_t addr) {
    asm volatile("ldmatrix.sync.aligned.m8n8.x4.trans.shared.b16 {%0,%1,%2,%3}, [%4];"
        : "=r"(r[0]), "=r"(r[1]), "=r"(r[2]), "=r"(r[3]) : "r"(addr));
}
__device__ __forceinline__ void mma_f16(float* c, const uint32_t* a, const uint32_t* b) {
    asm volatile(
        "mma.sync.aligned.m16n8k16.row.col.f32.f16.f16.f32 "
        "{%0,%1,%2,%3}, {%4,%5,%6,%7}, {%8,%9}, {%0,%1,%2,%3};"
        : "+f"(c[0]), "+f"(c[1]), "+f"(c[2]), "+f"(c[3])
        : "r"(a[0]), "r"(a[1]), "r"(a[2]), "r"(a[3]), "r"(b[0]), "r"(b[1]));
}

__device__ __forceinline__ uint32_t pk2h(__half a, __half b) {
    return (uint32_t)__half_as_ushort(a) | ((uint32_t)__half_as_ushort(b) << 16);
}

// ---------------- init ----------------
__global__ void zero_kernel() {
    int i = blockIdx.x * blockDim.x + threadIdx.x;
    if (i < NPAD) g_ltok[i] = -1;
    if (i < E_EXP) { g_count[i] = 0; g_smsum[i] = 0.0f; g_cursor[i] = 0; }
}

// ---------------- weight convert: fp32 -> fp16 ----------------
__global__ void convW_kernel(const float4* __restrict__ w1,
                             const float4* __restrict__ w2,
                             const float4* __restrict__ wp, int ysel, int n4) {
    int i = blockIdx.x * blockDim.x + threadIdx.x;
    if (i >= n4) return;
    int which = blockIdx.y + ysel;
    const float4* src;
    uint2* dst;
    if (which == 0)      { src = w1; dst = (uint2*)g_w1h; }
    else if (which == 1) { src = w2; dst = (uint2*)g_w2h; }
    else                 { src = wp; dst = (uint2*)g_wph; }
    float4 v = src[i];
    uint2 o;
    o.x = pk2h(__float2half_rn(v.x), __float2half_rn(v.y));
    o.y = pk2h(__float2half_rn(v.z), __float2half_rn(v.w));
    dst[i] = o;
}

// ---------------- gating: warp-per-token, block-accumulated stats ----------------
// grid 64 x 256 threads (8 warps); each warp handles 4 tokens.
__global__ __launch_bounds__(256) void gate_kernel(
        const float* __restrict__ x,
        const float* __restrict__ noise,
        const float* __restrict__ gw,
        const float* __restrict__ nw,
        float* __restrict__ out) {
    __shared__ float s_sm[E_EXP];
    __shared__ int   s_cnt[E_EXP];
    int tid = threadIdx.x, lane = tid & 31, warp = tid >> 5;
    if (tid < E_EXP) { s_sm[tid] = 0.0f; s_cnt[tid] = 0; }
    __syncthreads();

    #pragma unroll
    for (int i = 0; i < 4; i++) {
        int t = blockIdx.x * 32 + warp * 4 + i;
        const float* xr = x + (size_t)t * D_DIM;
        float acc[E_EXP];
        #pragma unroll
        for (int e = 0; e < E_EXP; e++) acc[e] = 0.0f;
        for (int d = lane; d < D_DIM; d += 32) {
            float xv = xr[d];
            const float* g = gw + d * E_EXP;
            #pragma unroll
            for (int e = 0; e < E_EXP; e++) acc[e] += xv * g[e];
        }
        #pragma unroll
        for (int e = 0; e < E_EXP; e++)
            #pragma unroll
            for (int o = 16; o; o >>= 1)
                acc[e] += __shfl_xor_sync(0xffffffffu, acc[e], o);

        if (lane == 0) {
            float m = -1e30f;
            #pragma unroll
            for (int e = 0; e < E_EXP; e++) m = fmaxf(m, acc[e]);
            float sum = 0.0f;
            float ex[E_EXP];
            #pragma unroll
            for (int e = 0; e < E_EXP; e++) { ex[e] = expf(acc[e] - m); sum += ex[e]; }
            float inv = 1.0f / sum;
            #pragma unroll
            for (int e = 0; e < E_EXP; e++) atomicAdd(&s_sm[e], ex[e] * inv);

            float ln[E_EXP];
            #pragma unroll
            for (int e = 0; e < E_EXP; e++) ln[e] = acc[e] + noise[t * E_EXP + e] * nw[e];

            int b0 = 0;
            #pragma unroll
            for (int e = 1; e < E_EXP; e++) if (ln[e] > ln[b0]) b0 = e;
            int b1 = (b0 == 0) ? 1 : 0;
            #pragma unroll
            for (int e = 0; e < E_EXP; e++) if (e != b0 && ln[e] > ln[b1]) b1 = e;

            float v0 = ln[b0], v1 = ln[b1];
            float mm = fmaxf(v0, v1);
            float e0 = expf(v0 - mm), e1 = expf(v1 - mm);
            float denom = 1.0f / (e0 + e1);

            g_e[t][0] = b0; g_e[t][1] = b1;
            g_g[t][0] = e0 * denom; g_g[t][1] = e1 * denom;
            atomicAdd(&s_cnt[b0], 1);
            atomicAdd(&s_cnt[b1], 1);
            out[OUT_IDS + t * K_TOP + 0] = (float)b0;
            out[OUT_IDS + t * K_TOP + 1] = (float)b1;
        }
    }
    __syncthreads();
    if (tid < E_EXP) {
        atomicAdd(&g_smsum[tid], s_sm[tid]);
        atomicAdd(&g_count[tid], s_cnt[tid]);
    }
}

// ---------------- padded offsets + lb loss ----------------
__global__ void offsets_kernel(float* __restrict__ out) {
    if (threadIdx.x == 0) {
        int acc = 0;
        #pragma unroll
        for (int e = 0; e < E_EXP; e++) {
            g_offset[e] = acc;
            acc += (g_count[e] + 127) & ~127;
        }
        g_offset[E_EXP] = acc;
        float loss = 0.0f;
        #pragma unroll
        for (int e = 0; e < E_EXP; e++) {
            float gm = g_smsum[e] / (float)T_TOK - 1.0f / (float)E_EXP;
            loss += gm * gm;
        }
        out[OUT_LOSS] = (loss / (float)E_EXP) * 0.01f;
    }
}

// ---------------- scatter ----------------
__global__ void scatter_kernel() {
    int t = blockIdx.x * blockDim.x + threadIdx.x;
    if (t >= T_TOK) return;
    #pragma unroll
    for (int k = 0; k < K_TOP; k++) {
        int e = g_e[t][k];
        int pos = atomicAdd(&g_cursor[e], 1);
        int r = g_offset[e] + pos;
        g_ltok[r] = t;
        g_slotgate[r] = g_g[t][k];
    }
}

// ---------------- gather routed x rows -> fp16 ----------------
__global__ void gatherx_kernel(const float* __restrict__ x) {
    int r = blockIdx.x;
    int d = threadIdx.x * 4;
    int t = g_ltok[r];
    uint2 uh = make_uint2(0, 0);
    if (t >= 0) {
        float4 v = *(const float4*)(x + (size_t)t * D_DIM + d);
        uh.x = pk2h(__float2half_rn(v.x), __float2half_rn(v.y));
        uh.y = pk2h(__float2half_rn(v.z), __float2half_rn(v.w));
    }
    *(uint2*)(g_xgh + (size_t)r * D_DIM + d) = uh;
}

// ---------------- HMMA grouped GEMM 1: act = (x@w1+b1)*silu(x@w2+b2) ----------------
__global__ __launch_bounds__(256) void gemm1_mma(
        const float* __restrict__ b1, const float* __restrict__ b2) {
    int e = blockIdx.z;
    int cnt = g_count[e];
    int m0 = blockIdx.x * 128;
    if (m0 >= cnt) return;
    int rbase = g_offset[e] + m0;
    int hb = blockIdx.y * 64;
    int tid = threadIdx.x;
    int lane = tid & 31, wid = tid >> 5;
    int wm = (wid & 3) * 32, wn = (wid >> 2) * 32;

    extern __shared__ char smraw[];
    __half* smb = (__half*)smraw;
    const int A_SZ = 128 * 40;
    const int B_SZ = 32 * 72;
    const int STG  = A_SZ + 2 * B_SZ;
    const uint32_t STGB = (uint32_t)STG * 2;

    int a_row = tid >> 1, a_half = tid & 1;
    int b_row = tid >> 3, b_col = (tid & 7) * 8;

    const __half* xh_p = g_xgh + (size_t)(rbase + a_row) * D_DIM + a_half * 16;
    const __half* w1_p = g_w1h + (size_t)e * D_DIM * H_DIM + hb + b_col;
    const __half* w2_p = g_w2h + (size_t)e * D_DIM * H_DIM + hb + b_col;

    uint32_t smbase = s2u(smb);
    uint32_t dAh = smbase + (uint32_t)(a_row * 40 + a_half * 16) * 2;
    uint32_t dB1 = smbase + (uint32_t)(A_SZ + b_row * 72 + b_col) * 2;
    uint32_t dB2 = dB1 + B_SZ * 2;

    float accH[2][4][4], accG[2][4][4];
    #pragma unroll
    for (int i = 0; i < 2; i++)
        #pragma unroll
        for (int j = 0; j < 4; j++)
            #pragma unroll
            for (int k = 0; k < 4; k++) { accH[i][j][k] = 0.f; accG[i][j][k] = 0.f; }

    const int NK = D_DIM / 32;   // 24

    {
        cp16(dAh, xh_p);  cp16(dAh + 16, xh_p + 8);
        size_t rk = (size_t)b_row * H_DIM;
        cp16(dB1, w1_p + rk);
        cp16(dB2, w2_p + rk);
        CP_COMMIT();
    }

    for (int kc = 0; kc < NK; kc++) {
        int p = kc & 1;
        if (kc + 1 < NK) {
            int k0 = (kc + 1) * 32;
            uint32_t so = (uint32_t)((kc + 1) & 1) * STGB;
            cp16(dAh + so, xh_p + k0);  cp16(dAh + so + 16, xh_p + k0 + 8);
            size_t rk = (size_t)(k0 + b_row) * H_DIM;
            cp16(dB1 + so, w1_p + rk);
            cp16(dB2 + so, w2_p + rk);
            CP_COMMIT();
            CP_WAIT1();
        } else {
            CP_WAIT0();
        }
        __syncthreads();

        __half* sAh = smb + p * STG;
        __half* sB1 = sAh + A_SZ;
        __half* sB2 = sB1 + B_SZ;

        #pragma unroll
        for (int k16 = 0; k16 < 32; k16 += 16) {
            uint32_t ah[2][4];
            #pragma unroll
            for (int mt = 0; mt < 2; mt++) {
                int ro = wm + mt * 16 + (lane & 15);
                int co = k16 + ((lane >> 4) << 3);
                ldsm4(ah[mt], s2u(sAh + ro * 40 + co));
            }
            #pragma unroll
            for (int q = 0; q < 2; q++) {
                int ro = k16 + (lane & 15);
                int co = wn + q * 16 + ((lane >> 4) << 3);
                uint32_t rb1[4], rb2[4];
                ldsm4t(rb1, s2u(sB1 + ro * 72 + co));
                ldsm4t(rb2, s2u(sB2 + ro * 72 + co));
                #pragma unroll
                for (int mt = 0; mt < 2; mt++)
                    #pragma unroll
                    for (int j = 0; j < 2; j++) {
                        mma_f16(accH[mt][q * 2 + j], ah[mt], &rb1[j * 2]);
                        mma_f16(accG[mt][q * 2 + j], ah[mt], &rb2[j * 2]);
                    }
            }
        }
        __syncthreads();
    }

    const float* b1p = b1 + (size_t)e * H_DIM + hb;
    const float* b2p = b2 + (size_t)e * H_DIM + hb;
    #pragma unroll
    for (int mt = 0; mt < 2; mt++) {
        int row0 = rbase + wm + mt * 16 + (lane >> 2);
        #pragma unroll
        for (int nt = 0; nt < 4; nt++) {
            int cl = wn + nt * 8 + (lane & 3) * 2;
            float bb1a = b1p[cl], bb1b = b1p[cl + 1];
            float bb2a = b2p[cl], bb2b = b2p[cl + 1];
            #pragma unroll
            for (int hf = 0; hf < 2; hf++) {
                float hv0 = accH[mt][nt][hf * 2 + 0] + bb1a;
                float hv1 = accH[mt][nt][hf * 2 + 1] + bb1b;
                float gv0 = accG[mt][nt][hf * 2 + 0] + bb2a;
                float gv1 = accG[mt][nt][hf * 2 + 1] + bb2b;
                float a0 = hv0 * (gv0 / (1.0f + expf(-gv0)));
                float a1 = hv1 * (gv1 / (1.0f + expf(-gv1)));
                uint32_t vh = pk2h(__float2half_rn(a0), __float2half_rn(a1));
                size_t off = (size_t)(row0 + hf * 8) * H_DIM + hb + cl;
                *(uint32_t*)(g_acth + off) = vh;
            }
        }
    }
}

// ---------------- HMMA grouped GEMM 2 (fused combine): out += gate*(act@wp + bp) ----------------
__global__ __launch_bounds__(256) void gemm2_mma(const float* __restrict__ bp,
                                                 float* __restrict__ out) {
    int e = blockIdx.z;
    int cnt = g_count[e];
    int m0 = blockIdx.x * 128;
    if (m0 >= cnt) return;
    int rbase = g_offset[e] + m0;
    int db = blockIdx.y * 128;
    int tid = threadIdx.x;
    int lane = tid & 31, wid = tid >> 5;
    int wm = (wid & 3) * 32, wn = (wid >> 2) * 64;

    extern __shared__ char smraw[];
    __half* smb = (__half*)smraw;
    const int A_SZ = 128 * 40;
    const int B_SZ = 32 * 136;
    const int STG  = A_SZ + B_SZ;
    const uint32_t STGB = (uint32_t)STG * 2;

    int a_row = tid >> 1, a_half = tid & 1;
    int b_row = tid >> 3, b_col = (tid & 7) * 16;

    const __half* ah_p = g_acth + (size_t)(rbase + a_row) * H_DIM + a_half * 16;
    const __half* wp_p = g_wph + (size_t)e * H_DIM * D_DIM + db + b_col;

    uint32_t smbase = s2u(smb);
    uint32_t dAh = smbase + (uint32_t)(a_row * 40 + a_half * 16) * 2;
    uint32_t dB  = smbase + (uint32_t)(A_SZ + b_row * 136 + b_col) * 2;

    float acc[2][8][4];
    #pragma unroll
    for (int i = 0; i < 2; i++)
        #pragma unroll
        for (int j = 0; j < 8; j++)
            #pragma unroll
            for (int k = 0; k < 4; k++) acc[i][j][k] = 0.f;

    const int NK = H_DIM / 32;   // 96

    {
        cp16(dAh, ah_p);  cp16(dAh + 16, ah_p + 8);
        size_t rk = (size_t)b_row * D_DIM;
        cp16(dB, wp_p + rk);  cp16(dB + 16, wp_p + rk + 8);
        CP_COMMIT();
    }

    for (int kc = 0; kc < NK; kc++) {
        int p = kc & 1;
        if (kc + 1 < NK) {
            int k0 = (kc + 1) * 32;
            uint32_t so = (uint32_t)((kc + 1) & 1) * STGB;
            cp16(dAh + so, ah_p + k0);  cp16(dAh + so + 16, ah_p + k0 + 8);
            size_t rk = (size_t)(k0 + b_row) * D_DIM;
            cp16(dB + so, wp_p + rk);  cp16(dB + so + 16, wp_p + rk + 8);
            CP_COMMIT();
            CP_WAIT1();
        } else {
            CP_WAIT0();
        }
        __syncthreads();

        __half* sAh = smb + p * STG;
        __half* sB  = sAh + A_SZ;

        #pragma unroll
        for (int k16 = 0; k16 < 32; k16 += 16) {
            uint32_t ah[2][4];
            #pragma unroll
            for (int mt = 0; mt < 2; mt++) {
                int ro = wm + mt * 16 + (lane & 15);
                int co = k16 + ((lane >> 4) << 3);
                ldsm4(ah[mt], s2u(sAh + ro * 40 + co));
            }
            #pragma unroll
            for (int q = 0; q < 4; q++) {
                int ro = k16 + (lane & 15);
                int co = wn + q * 16 + ((lane >> 4) << 3);
                uint32_t rb[4];
                ldsm4t(rb, s2u(sB + ro * 136 + co));
                #pragma unroll
                for (int mt = 0; mt < 2; mt++)
                    #pragma unroll
                    for (int j = 0; j < 2; j++)
                        mma_f16(acc[mt][q * 2 + j], ah[mt], &rb[j * 2]);
            }
        }
        __syncthreads();
    }

    // fused combine epilogue: out[t] += gate * (acc + bp)
    const float* bpp = bp + (size_t)e * D_DIM + db;
    #pragma unroll
    for (int mt = 0; mt < 2; mt++) {
        int rb0 = rbase + wm + mt * 16 + (lane >> 2);
        #pragma unroll
        for (int hf = 0; hf < 2; hf++) {
            int r = rb0 + hf * 8;
            int t = g_ltok[r];
            if (t < 0) continue;
            float gt = g_slotgate[r];
            float* orow = out + (size_t)t * D_DIM + db;
            #pragma unroll
            for (int nt = 0; nt < 8; nt++) {
                int cl = wn + nt * 8 + (lane & 3) * 2;
                atomicAdd(&orow[cl],     gt * (acc[mt][nt][hf * 2 + 0] + bpp[cl]));
                atomicAdd(&orow[cl + 1], gt * (acc[mt][nt][hf * 2 + 1] + bpp[cl + 1]));
            }
        }
    }
}

// ---------------- launch ----------------
extern "C" void kernel_launch(void* const* d_in, const int* in_sizes, int n_in,
                              void* d_out, int out_size) {
    const float* x     = (const float*)d_in[0];
    const float* noise = (const float*)d_in[1];
    const float* gw    = (const float*)d_in[2];
    const float* nw    = (const float*)d_in[3];
    const float* w1    = (const float*)d_in[4];
    const float* b1    = (const float*)d_in[5];
    const float* w2    = (const float*)d_in[6];
    const float* b2    = (const float*)d_in[7];
    const float* wp    = (const float*)d_in[8];
    const float* bp    = (const float*)d_in[9];
    float* out = (float*)d_out;

    const int SM1 = 2 * (128 * 40 + 2 * 32 * 72) * 2;   // 38912 B
    const int SM2 = 2 * (128 * 40 + 32 * 136) * 2;      // 37888 B
    cudaFuncSetAttribute(gemm1_mma, cudaFuncAttributeMaxDynamicSharedMemorySize, SM1);
    cudaFuncSetAttribute(gemm2_mma, cudaFuncAttributeMaxDynamicSharedMemorySize, SM2);

    static cudaStream_t s2 = nullptr;
    static cudaEvent_t evFork = nullptr, evW12 = nullptr, evWp = nullptr;
    if (s2 == nullptr) {
        cudaStreamCreateWithFlags(&s2, cudaStreamNonBlocking);
        cudaEventCreateWithFlags(&evFork, cudaEventDisableTiming);
        cudaEventCreateWithFlags(&evW12, cudaEventDisableTiming);
        cudaEventCreateWithFlags(&evWp, cudaEventDisableTiming);
    }

    const int NW4 = E_EXP * D_DIM * H_DIM / 4;

    // fork: weight conversion on side stream
    cudaEventRecord(evFork, 0);
    cudaStreamWaitEvent(s2, evFork, 0);
    convW_kernel<<<dim3((NW4 + 255) / 256, 2), 256, 0, s2>>>(
        (const float4*)w1, (const float4*)w2, (const float4*)wp, 0, NW4);
    cudaEventRecord(evW12, s2);
    convW_kernel<<<dim3((NW4 + 255) / 256, 1), 256, 0, s2>>>(
        (const float4*)w1, (const float4*)w2, (const float4*)wp, 2, NW4);
    cudaEventRecord(evWp, s2);

    // main stream: prologue chain (out zeroed for fused-combine atomics)
    cudaMemsetAsync(out, 0, (size_t)T_TOK * D_DIM * sizeof(float));
    zero_kernel<<<(NPAD + 255) / 256, 256>>>();
    gate_kernel<<<64, 256>>>(x, noise, gw, nw, out);
    offsets_kernel<<<1, 32>>>(out);
    scatter_kernel<<<(T_TOK + 255) / 256, 256>>>();
    gatherx_kernel<<<NPAD, 192>>>(x);

    // join: gemm1 needs w1,w2; gemm2 needs wp
    cudaStreamWaitEvent(0, evW12, 0);
    gemm1_mma<<<dim3(16, H_DIM / 64, E_EXP), 256, SM1>>>(b1, b2);
    cudaStreamWaitEvent(0, evWp, 0);
    gemm2_mma<<<dim3(16, D_DIM / 128, E_EXP), 256, SM2>>>(bp, out);
}

// round 15
// speedup vs baseline: 1.6382x; 1.6382x over previous
#include <cuda_runtime.h>
#include <cuda_fp16.h>
#include <math.h>
#include <stdint.h>

#define T_TOK 2048
#define D_DIM 768
#define E_EXP 8
#define K_TOP 2
#define H_DIM 3072
#define NPAD  5120

#define OUT_IDS  (T_TOK * D_DIM)
#define OUT_LOSS (T_TOK * D_DIM + T_TOK * K_TOP)

// ---------------- device scratch ----------------
__device__ int   g_e[T_TOK][K_TOP];
__device__ float g_g[T_TOK][K_TOP];
__device__ int   g_rows[T_TOK][K_TOP];
__device__ int   g_count[E_EXP];
__device__ int   g_offset[E_EXP + 1];
__device__ int   g_cursor[E_EXP];
__device__ float g_smsum[E_EXP];
__device__ int   g_ltok[NPAD];

__device__ __half g_xgh[(size_t)NPAD * D_DIM];
__device__ __half g_w1h[(size_t)E_EXP * D_DIM * H_DIM];
__device__ __half g_w2h[(size_t)E_EXP * D_DIM * H_DIM];
__device__ __half g_wph[(size_t)E_EXP * H_DIM * D_DIM];
__device__ __half g_acth[(size_t)NPAD * H_DIM];
__device__ float g_y[(size_t)NPAD * D_DIM];

// ---------------- helpers ----------------
__device__ __forceinline__ uint32_t s2u(const void* p) {
    return (uint32_t)__cvta_generic_to_shared(p);
}
__device__ __forceinline__ void cp16(uint32_t dst, const void* src) {
    asm volatile("cp.async.ca.shared.global [%0], [%1], 16;" :: "r"(dst), "l"(src));
}
#define CP_COMMIT() asm volatile("cp.async.commit_group;")
#define CP_WAIT1()  asm volatile("cp.async.wait_group 1;")
#define CP_WAIT0()  asm volatile("cp.async.wait_group 0;")

__device__ __forceinline__ void ldsm4(uint32_t* r, uint32_t addr) {
    asm volatile("ldmatrix.sync.aligned.m8n8.x4.shared.b16 {%0,%1,%2,%3}, [%4];"
        : "=r"(r[0]), "=r"(r[1]), "=r"(r[2]), "=r"(r[3]) : "r"(addr));
}
__device__ __forceinline__ void ldsm4t(uint32_t* r, uint32_t addr) {
    asm volatile("ldmatrix.sync.aligned.m8n8.x4.trans.shared.b16 {%0,%1,%2,%3}, [%4];"
        : "=r"(r[0]), "=r"(r[1]), "=r"(r[2]), "=r"(r[3]) : "r"(addr));
}
__device__ __forceinline__ void mma_f16(float* c, const uint32_t* a, const uint32_t* b) {
    asm volatile(
        "mma.sync.aligned.m16n8k16.row.col.f32.f16.f16.f32 "
        "{%0,%1,%2,%3}, {%4,%5,%6,%7}, {%8,%9}, {%0,%1,%2,%3};"
        : "+f"(c[0]), "+f"(c[1]), "+f"(c[2]), "+f"(c[3])
        : "r"(a[0]), "r"(a[1]), "r"(a[2]), "r"(a[3]), "r"(b[0]), "r"(b[1]));
}

__device__ __forceinline__ uint32_t pk2h(__half a, __half b) {
    return (uint32_t)__half_as_ushort(a) | ((uint32_t)__half_as_ushort(b) << 16);
}

// ---------------- init ----------------
__global__ void zero_kernel() {
    int i = blockIdx.x * blockDim.x + threadIdx.x;
    if (i < NPAD) g_ltok[i] = -1;
    if (i < E_EXP) { g_count[i] = 0; g_smsum[i] = 0.0f; g_cursor[i] = 0; }
}

// ---------------- weight convert: fp32 -> fp16 ----------------
__global__ void convW_kernel(const float4* __restrict__ w1,
                             const float4* __restrict__ w2,
                             const float4* __restrict__ wp, int ysel, int n4) {
    int i = blockIdx.x * blockDim.x + threadIdx.x;
    if (i >= n4) return;
    int which = blockIdx.y + ysel;
    const float4* src;
    uint2* dst;
    if (which == 0)      { src = w1; dst = (uint2*)g_w1h; }
    else if (which == 1) { src = w2; dst = (uint2*)g_w2h; }
    else                 { src = wp; dst = (uint2*)g_wph; }
    float4 v = src[i];
    uint2 o;
    o.x = pk2h(__float2half_rn(v.x), __float2half_rn(v.y));
    o.y = pk2h(__float2half_rn(v.z), __float2half_rn(v.w));
    dst[i] = o;
}

// ---------------- gating: warp-per-token, 8 tokens/block, 256 blocks ----------------
__global__ __launch_bounds__(256) void gate_kernel(
        const float* __restrict__ x,
        const float* __restrict__ noise,
        const float* __restrict__ gw,
        const float* __restrict__ nw,
        float* __restrict__ out) {
    __shared__ float s_sm[E_EXP];
    __shared__ int   s_cnt[E_EXP];
    int tid = threadIdx.x, lane = tid & 31, warp = tid >> 5;
    if (tid < E_EXP) { s_sm[tid] = 0.0f; s_cnt[tid] = 0; }
    __syncthreads();

    int t = blockIdx.x * 8 + warp;
    const float* xr = x + (size_t)t * D_DIM;
    float acc[E_EXP];
    #pragma unroll
    for (int e = 0; e < E_EXP; e++) acc[e] = 0.0f;
    for (int d = lane; d < D_DIM; d += 32) {
        float xv = xr[d];
        const float* g = gw + d * E_EXP;
        #pragma unroll
        for (int e = 0; e < E_EXP; e++) acc[e] += xv * g[e];
    }
    #pragma unroll
    for (int e = 0; e < E_EXP; e++)
        #pragma unroll
        for (int o = 16; o; o >>= 1)
            acc[e] += __shfl_xor_sync(0xffffffffu, acc[e], o);

    if (lane == 0) {
        float m = -1e30f;
        #pragma unroll
        for (int e = 0; e < E_EXP; e++) m = fmaxf(m, acc[e]);
        float sum = 0.0f;
        float ex[E_EXP];
        #pragma unroll
        for (int e = 0; e < E_EXP; e++) { ex[e] = expf(acc[e] - m); sum += ex[e]; }
        float inv = 1.0f / sum;
        #pragma unroll
        for (int e = 0; e < E_EXP; e++) atomicAdd(&s_sm[e], ex[e] * inv);

        float ln[E_EXP];
        #pragma unroll
        for (int e = 0; e < E_EXP; e++) ln[e] = acc[e] + noise[t * E_EXP + e] * nw[e];

        int b0 = 0;
        #pragma unroll
        for (int e = 1; e < E_EXP; e++) if (ln[e] > ln[b0]) b0 = e;
        int b1 = (b0 == 0) ? 1 : 0;
        #pragma unroll
        for (int e = 0; e < E_EXP; e++) if (e != b0 && ln[e] > ln[b1]) b1 = e;

        float v0 = ln[b0], v1 = ln[b1];
        float mm = fmaxf(v0, v1);
        float e0 = expf(v0 - mm), e1 = expf(v1 - mm);
        float denom = 1.0f / (e0 + e1);

        g_e[t][0] = b0; g_e[t][1] = b1;
        g_g[t][0] = e0 * denom; g_g[t][1] = e1 * denom;
        atomicAdd(&s_cnt[b0], 1);
        atomicAdd(&s_cnt[b1], 1);
        out[OUT_IDS + t * K_TOP + 0] = (float)b0;
        out[OUT_IDS + t * K_TOP + 1] = (float)b1;
    }
    __syncthreads();
    if (tid < E_EXP) {
        atomicAdd(&g_smsum[tid], s_sm[tid]);
        atomicAdd(&g_count[tid], s_cnt[tid]);
    }
}

// ---------------- padded offsets + lb loss ----------------
__global__ void offsets_kernel(float* __restrict__ out) {
    if (threadIdx.x == 0) {
        int acc = 0;
        #pragma unroll
        for (int e = 0; e < E_EXP; e++) {
            g_offset[e] = acc;
            acc += (g_count[e] + 127) & ~127;
        }
        g_offset[E_EXP] = acc;
        float loss = 0.0f;
        #pragma unroll
        for (int e = 0; e < E_EXP; e++) {
            float gm = g_smsum[e] / (float)T_TOK - 1.0f / (float)E_EXP;
            loss += gm * gm;
        }
        out[OUT_LOSS] = (loss / (float)E_EXP) * 0.01f;
    }
}

// ---------------- scatter ----------------
__global__ void scatter_kernel() {
    int t = blockIdx.x * blockDim.x + threadIdx.x;
    if (t >= T_TOK) return;
    #pragma unroll
    for (int k = 0; k < K_TOP; k++) {
        int e = g_e[t][k];
        int pos = atomicAdd(&g_cursor[e], 1);
        int r = g_offset[e] + pos;
        g_ltok[r] = t;
        g_rows[t][k] = r;
    }
}

// ---------------- gather routed x rows -> fp16 ----------------
__global__ void gatherx_kernel(const float* __restrict__ x) {
    int r = blockIdx.x;
    int d = threadIdx.x * 4;
    int t = g_ltok[r];
    uint2 uh = make_uint2(0, 0);
    if (t >= 0) {
        float4 v = *(const float4*)(x + (size_t)t * D_DIM + d);
        uh.x = pk2h(__float2half_rn(v.x), __float2half_rn(v.y));
        uh.y = pk2h(__float2half_rn(v.z), __float2half_rn(v.w));
    }
    *(uint2*)(g_xgh + (size_t)r * D_DIM + d) = uh;
}

// ---------------- HMMA grouped GEMM 1: act = (x@w1+b1)*silu(x@w2+b2) ----------------
__global__ __launch_bounds__(256) void gemm1_mma(
        const float* __restrict__ b1, const float* __restrict__ b2) {
    int e = blockIdx.z;
    int cnt = g_count[e];
    int m0 = blockIdx.x * 128;
    if (m0 >= cnt) return;
    int rbase = g_offset[e] + m0;
    int hb = blockIdx.y * 64;
    int tid = threadIdx.x;
    int lane = tid & 31, wid = tid >> 5;
    int wm = (wid & 3) * 32, wn = (wid >> 2) * 32;

    extern __shared__ char smraw[];
    __half* smb = (__half*)smraw;
    const int A_SZ = 128 * 40;
    const int B_SZ = 32 * 72;
    const int STG  = A_SZ + 2 * B_SZ;
    const uint32_t STGB = (uint32_t)STG * 2;

    int a_row = tid >> 1, a_half = tid & 1;
    int b_row = tid >> 3, b_col = (tid & 7) * 8;

    const __half* xh_p = g_xgh + (size_t)(rbase + a_row) * D_DIM + a_half * 16;
    const __half* w1_p = g_w1h + (size_t)e * D_DIM * H_DIM + hb + b_col;
    const __half* w2_p = g_w2h + (size_t)e * D_DIM * H_DIM + hb + b_col;

    uint32_t smbase = s2u(smb);
    uint32_t dAh = smbase + (uint32_t)(a_row * 40 + a_half * 16) * 2;
    uint32_t dB1 = smbase + (uint32_t)(A_SZ + b_row * 72 + b_col) * 2;
    uint32_t dB2 = dB1 + B_SZ * 2;

    float accH[2][4][4], accG[2][4][4];
    #pragma unroll
    for (int i = 0; i < 2; i++)
        #pragma unroll
        for (int j = 0; j < 4; j++)
            #pragma unroll
            for (int k = 0; k < 4; k++) { accH[i][j][k] = 0.f; accG[i][j][k] = 0.f; }

    const int NK = D_DIM / 32;   // 24

    {
        cp16(dAh, xh_p);  cp16(dAh + 16, xh_p + 8);
        size_t rk = (size_t)b_row * H_DIM;
        cp16(dB1, w1_p + rk);
        cp16(dB2, w2_p + rk);
        CP_COMMIT();
    }

    for (int kc = 0; kc < NK; kc++) {
        int p = kc & 1;
        if (kc + 1 < NK) {
            int k0 = (kc + 1) * 32;
            uint32_t so = (uint32_t)((kc + 1) & 1) * STGB;
            cp16(dAh + so, xh_p + k0);  cp16(dAh + so + 16, xh_p + k0 + 8);
            size_t rk = (size_t)(k0 + b_row) * H_DIM;
            cp16(dB1 + so, w1_p + rk);
            cp16(dB2 + so, w2_p + rk);
            CP_COMMIT();
            CP_WAIT1();
        } else {
            CP_WAIT0();
        }
        __syncthreads();

        __half* sAh = smb + p * STG;
        __half* sB1 = sAh + A_SZ;
        __half* sB2 = sB1 + B_SZ;

        #pragma unroll
        for (int k16 = 0; k16 < 32; k16 += 16) {
            uint32_t ah[2][4];
            #pragma unroll
            for (int mt = 0; mt < 2; mt++) {
                int ro = wm + mt * 16 + (lane & 15);
                int co = k16 + ((lane >> 4) << 3);
                ldsm4(ah[mt], s2u(sAh + ro * 40 + co));
            }
            #pragma unroll
            for (int q = 0; q < 2; q++) {
                int ro = k16 + (lane & 15);
                int co = wn + q * 16 + ((lane >> 4) << 3);
                uint32_t rb1[4], rb2[4];
                ldsm4t(rb1, s2u(sB1 + ro * 72 + co));
                ldsm4t(rb2, s2u(sB2 + ro * 72 + co));
                #pragma unroll
                for (int mt = 0; mt < 2; mt++)
                    #pragma unroll
                    for (int j = 0; j < 2; j++) {
                        mma_f16(accH[mt][q * 2 + j], ah[mt], &rb1[j * 2]);
                        mma_f16(accG[mt][q * 2 + j], ah[mt], &rb2[j * 2]);
                    }
            }
        }
        __syncthreads();
    }

    const float* b1p = b1 + (size_t)e * H_DIM + hb;
    const float* b2p = b2 + (size_t)e * H_DIM + hb;
    #pragma unroll
    for (int mt = 0; mt < 2; mt++) {
        int row0 = rbase + wm + mt * 16 + (lane >> 2);
        #pragma unroll
        for (int nt = 0; nt < 4; nt++) {
            int cl = wn + nt * 8 + (lane & 3) * 2;
            float bb1a = b1p[cl], bb1b = b1p[cl + 1];
            float bb2a = b2p[cl], bb2b = b2p[cl + 1];
            #pragma unroll
            for (int hf = 0; hf < 2; hf++) {
                float hv0 = accH[mt][nt][hf * 2 + 0] + bb1a;
                float hv1 = accH[mt][nt][hf * 2 + 1] + bb1b;
                float gv0 = accG[mt][nt][hf * 2 + 0] + bb2a;
                float gv1 = accG[mt][nt][hf * 2 + 1] + bb2b;
                float a0 = hv0 * (gv0 / (1.0f + expf(-gv0)));
                float a1 = hv1 * (gv1 / (1.0f + expf(-gv1)));
                uint32_t vh = pk2h(__float2half_rn(a0), __float2half_rn(a1));
                size_t off = (size_t)(row0 + hf * 8) * H_DIM + hb + cl;
                *(uint32_t*)(g_acth + off) = vh;
            }
        }
    }
}

// ---------------- HMMA grouped GEMM 2: y = act @ wp + bp ----------------
__global__ __launch_bounds__(256) void gemm2_mma(const float* __restrict__ bp) {
    int e = blockIdx.z;
    int cnt = g_count[e];
    int m0 = blockIdx.x * 128;
    if (m0 >= cnt) return;
    int rbase = g_offset[e] + m0;
    int db = blockIdx.y * 128;
    int tid = threadIdx.x;
    int lane = tid & 31, wid = tid >> 5;
    int wm = (wid & 3) * 32, wn = (wid >> 2) * 64;

    extern __shared__ char smraw[];
    __half* smb = (__half*)smraw;
    const int A_SZ = 128 * 40;
    const int B_SZ = 32 * 136;
    const int STG  = A_SZ + B_SZ;
    const uint32_t STGB = (uint32_t)STG * 2;

    int a_row = tid >> 1, a_half = tid & 1;
    int b_row = tid >> 3, b_col = (tid & 7) * 16;

    const __half* ah_p = g_acth + (size_t)(rbase + a_row) * H_DIM + a_half * 16;
    const __half* wp_p = g_wph + (size_t)e * H_DIM * D_DIM + db + b_col;

    uint32_t smbase = s2u(smb);
    uint32_t dAh = smbase + (uint32_t)(a_row * 40 + a_half * 16) * 2;
    uint32_t dB  = smbase + (uint32_t)(A_SZ + b_row * 136 + b_col) * 2;

    float acc[2][8][4];
    #pragma unroll
    for (int i = 0; i < 2; i++)
        #pragma unroll
        for (int j = 0; j < 8; j++)
            #pragma unroll
            for (int k = 0; k < 4; k++) acc[i][j][k] = 0.f;

    const int NK = H_DIM / 32;   // 96

    {
        cp16(dAh, ah_p);  cp16(dAh + 16, ah_p + 8);
        size_t rk = (size_t)b_row * D_DIM;
        cp16(dB, wp_p + rk);  cp16(dB + 16, wp_p + rk + 8);
        CP_COMMIT();
    }

    for (int kc = 0; kc < NK; kc++) {
        int p = kc & 1;
        if (kc + 1 < NK) {
            int k0 = (kc + 1) * 32;
            uint32_t so = (uint32_t)((kc + 1) & 1) * STGB;
            cp16(dAh + so, ah_p + k0);  cp16(dAh + so + 16, ah_p + k0 + 8);
            size_t rk = (size_t)(k0 + b_row) * D_DIM;
            cp16(dB + so, wp_p + rk);  cp16(dB + so + 16, wp_p + rk + 8);
            CP_COMMIT();
            CP_WAIT1();
        } else {
            CP_WAIT0();
        }
        __syncthreads();

        __half* sAh = smb + p * STG;
        __half* sB  = sAh + A_SZ;

        #pragma unroll
        for (int k16 = 0; k16 < 32; k16 += 16) {
            uint32_t ah[2][4];
            #pragma unroll
            for (int mt = 0; mt < 2; mt++) {
                int ro = wm + mt * 16 + (lane & 15);
                int co = k16 + ((lane >> 4) << 3);
                ldsm4(ah[mt], s2u(sAh + ro * 40 + co));
            }
            #pragma unroll
            for (int q = 0; q < 4; q++) {
                int ro = k16 + (lane & 15);
                int co = wn + q * 16 + ((lane >> 4) << 3);
                uint32_t rb[4];
                ldsm4t(rb, s2u(sB + ro * 136 + co));
                #pragma unroll
                for (int mt = 0; mt < 2; mt++)
                    #pragma unroll
                    for (int j = 0; j < 2; j++)
                        mma_f16(acc[mt][q * 2 + j], ah[mt], &rb[j * 2]);
            }
        }
        __syncthreads();
    }

    const float* bpp = bp + (size_t)e * D_DIM + db;
    #pragma unroll
    for (int mt = 0; mt < 2; mt++) {
        int row0 = rbase + wm + mt * 16 + (lane >> 2);
        #pragma unroll
        for (int nt = 0; nt < 8; nt++) {
            int cl = wn + nt * 8 + (lane & 3) * 2;
            float ba = bpp[cl], bb = bpp[cl + 1];
            #pragma unroll
            for (int hf = 0; hf < 2; hf++) {
                float2 v;
                v.x = acc[mt][nt][hf * 2 + 0] + ba;
                v.y = acc[mt][nt][hf * 2 + 1] + bb;
                *(float2*)(g_y + (size_t)(row0 + hf * 8) * D_DIM + db + cl) = v;
            }
        }
    }
}

// ---------------- final combine: out[t] = g0*y[r0] + g1*y[r1] ----------------
__global__ void combine_kernel(float* __restrict__ out) {
    int t = blockIdx.x;
    int d = threadIdx.x * 4;
    int r0 = g_rows[t][0], r1 = g_rows[t][1];
    float g0 = g_g[t][0], g1 = g_g[t][1];
    float4 a = *(const float4*)(g_y + (size_t)r0 * D_DIM + d);
    float4 b = *(const float4*)(g_y + (size_t)r1 * D_DIM + d);
    float4 o;
    o.x = g0 * a.x + g1 * b.x;
    o.y = g0 * a.y + g1 * b.y;
    o.z = g0 * a.z + g1 * b.z;
    o.w = g0 * a.w + g1 * b.w;
    *(float4*)(out + (size_t)t * D_DIM + d) = o;
}

// ---------------- launch ----------------
extern "C" void kernel_launch(void* const* d_in, const int* in_sizes, int n_in,
                              void* d_out, int out_size) {
    const float* x     = (const float*)d_in[0];
    const float* noise = (const float*)d_in[1];
    const float* gw    = (const float*)d_in[2];
    const float* nw    = (const float*)d_in[3];
    const float* w1    = (const float*)d_in[4];
    const float* b1    = (const float*)d_in[5];
    const float* w2    = (const float*)d_in[6];
    const float* b2    = (const float*)d_in[7];
    const float* wp    = (const float*)d_in[8];
    const float* bp    = (const float*)d_in[9];
    float* out = (float*)d_out;

    const int SM1 = 2 * (128 * 40 + 2 * 32 * 72) * 2;   // 38912 B
    const int SM2 = 2 * (128 * 40 + 32 * 136) * 2;      // 37888 B
    cudaFuncSetAttribute(gemm1_mma, cudaFuncAttributeMaxDynamicSharedMemorySize, SM1);
    cudaFuncSetAttribute(gemm2_mma, cudaFuncAttributeMaxDynamicSharedMemorySize, SM2);

    static cudaStream_t s2 = nullptr;
    static cudaEvent_t evFork = nullptr, evW12 = nullptr, evWp = nullptr;
    if (s2 == nullptr) {
        cudaStreamCreateWithFlags(&s2, cudaStreamNonBlocking);
        cudaEventCreateWithFlags(&evFork, cudaEventDisableTiming);
        cudaEventCreateWithFlags(&evW12, cudaEventDisableTiming);
        cudaEventCreateWithFlags(&evWp, cudaEventDisableTiming);
    }

    const int NW4 = E_EXP * D_DIM * H_DIM / 4;

    // fork: weight conversion on side stream
    cudaEventRecord(evFork, 0);
    cudaStreamWaitEvent(s2, evFork, 0);
    convW_kernel<<<dim3((NW4 + 255) / 256, 2), 256, 0, s2>>>(
        (const float4*)w1, (const float4*)w2, (const float4*)wp, 0, NW4);
    cudaEventRecord(evW12, s2);
    convW_kernel<<<dim3((NW4 + 255) / 256, 1), 256, 0, s2>>>(
        (const float4*)w1, (const float4*)w2, (const float4*)wp, 2, NW4);
    cudaEventRecord(evWp, s2);

    // main stream: prologue chain
    zero_kernel<<<(NPAD + 255) / 256, 256>>>();
    gate_kernel<<<T_TOK / 8, 256>>>(x, noise, gw, nw, out);
    offsets_kernel<<<1, 32>>>(out);
    scatter_kernel<<<(T_TOK + 255) / 256, 256>>>();
    gatherx_kernel<<<NPAD, 192>>>(x);

    // join: gemm1 needs w1,w2; gemm2 needs wp
    cudaStreamWaitEvent(0, evW12, 0);
    gemm1_mma<<<dim3(16, H_DIM / 64, E_EXP), 256, SM1>>>(b1, b2);
    cudaStreamWaitEvent(0, evWp, 0);
    gemm2_mma<<<dim3(16, D_DIM / 128, E_EXP), 256, SM2>>>(bp);

    combine_kernel<<<T_TOK, 192>>>(out);
}